// round 1
// baseline (speedup 1.0000x reference)
#include <cuda_runtime.h>
#include <cstdint>

// Problem: out[m, o] = sum_d FWHT(x)[m, d] * W[o, d] * (1/sqrt(D)) + b[o]
// Since the Sylvester Hadamard H is symmetric:
//   FWHT(x) @ W^T == x @ (FWHT_rows(W))^T
// So we transform W's rows (2048 rows, cheap) instead of x's 16384 rows,
// then run a single NT GEMM:  C[M,N] = A[M,K] * Wh[N,K]^T + b.

#define D_DIM 2048

// Device-global scratch for the Hadamard-transformed weight (16 MB).
// (Allocation APIs are banned; __device__ globals are the sanctioned scratch.)
__device__ float g_Wh[D_DIM * (size_t)D_DIM];

// ---------------------------------------------------------------------------
// Kernel 1: FWHT along the last dim of W (one block per row), scale folded in.
// ---------------------------------------------------------------------------
__global__ __launch_bounds__(256) void fwht_rows_kernel(const float* __restrict__ W) {
    __shared__ float s[D_DIM];
    const float* row = W + (size_t)blockIdx.x * D_DIM;
    int tid = threadIdx.x;

    for (int i = tid; i < D_DIM; i += 256) s[i] = row[i];
    __syncthreads();

    #pragma unroll
    for (int lg = 0; lg < 11; lg++) {           // 2^11 = 2048
        int h = 1 << lg;
        #pragma unroll
        for (int q = 0; q < (D_DIM / 2) / 256; q++) {
            int p = tid + q * 256;
            int i = ((p >> lg) << (lg + 1)) | (p & (h - 1));
            float a = s[i];
            float c = s[i + h];
            s[i]     = a + c;
            s[i + h] = a - c;
        }
        __syncthreads();
    }

    const float scale = 0.02209708691207961f;   // 1/sqrt(2048) = 2^-5.5
    float* dst = g_Wh + (size_t)blockIdx.x * D_DIM;
    for (int i = tid; i < D_DIM; i += 256) dst[i] = s[i] * scale;
}

// ---------------------------------------------------------------------------
// Kernel 2: NT GEMM with packed f32x2 FMA (Blackwell fma.rn.f32x2).
//   C[m,n] = sum_k A[m,k] * Wh[n,k] + bias[n]
// Tiles: BM=BN=128, BK=16, 256 threads, 8x8 per-thread microtile,
// double-buffered smem, K-transposed tiles with stride-136 padding.
// ---------------------------------------------------------------------------
#define BM 128
#define BN 128
#define BK 16
#define SPAD 136   // padded row stride (floats): makes transpose STS conflict-free

typedef unsigned long long u64;

__device__ __forceinline__ u64 pack2(float v) {
    u64 r;
    unsigned int u = __float_as_uint(v);
    asm("mov.b64 %0, {%1, %2};" : "=l"(r) : "r"(u), "r"(u));
    return r;
}
__device__ __forceinline__ u64 ffma2(u64 a, u64 b, u64 c) {
    u64 d;
    asm("fma.rn.f32x2 %0, %1, %2, %3;" : "=l"(d) : "l"(a), "l"(b), "l"(c));
    return d;
}
__device__ __forceinline__ void unpack2(u64 v, float& lo, float& hi) {
    unsigned int a, b;
    asm("mov.b64 {%0, %1}, %2;" : "=r"(a), "=r"(b) : "l"(v));
    lo = __uint_as_float(a);
    hi = __uint_as_float(b);
}

__global__ __launch_bounds__(256, 2)
void had_gemm_kernel(const float* __restrict__ A,
                     const float* __restrict__ bias,
                     float* __restrict__ C,
                     int M, int N, int K) {
    __shared__ float As[2][BK][SPAD];
    __shared__ float Bs[2][BK][SPAD];

    const float* B = g_Wh;

    const int tid = threadIdx.x;
    const int bm  = blockIdx.y * BM;
    const int bn  = blockIdx.x * BN;

    // compute-thread mapping: 16x16 grid of threads, each owns 8x8 outputs
    const int tx = tid & 15;
    const int ty = tid >> 4;
    const int m0 = ty * 8;
    const int n0 = tx * 8;

    // load mapping: 512 float4 per tile per matrix; 2 per thread
    const int lr = tid >> 2;          // 0..63  (row within tile, +64 for 2nd)
    const int lk = (tid & 3) * 4;     // 0,4,8,12 (k offset, float4 granule)

    const float* gA0 = A + (size_t)(bm + lr)      * K + lk;
    const float* gA1 = A + (size_t)(bm + lr + 64) * K + lk;
    const float* gB0 = B + (size_t)(bn + lr)      * K + lk;
    const float* gB1 = B + (size_t)(bn + lr + 64) * K + lk;

    u64 acc[8][4];
    #pragma unroll
    for (int i = 0; i < 8; i++)
        #pragma unroll
        for (int j = 0; j < 4; j++)
            acc[i][j] = 0ull;

    float4 ra0, ra1, rb0, rb1;

    // ---- prologue: tile 0 -> smem buf 0
    ra0 = *(const float4*)(gA0);
    ra1 = *(const float4*)(gA1);
    rb0 = *(const float4*)(gB0);
    rb1 = *(const float4*)(gB1);

    As[0][lk + 0][lr] = ra0.x; As[0][lk + 1][lr] = ra0.y;
    As[0][lk + 2][lr] = ra0.z; As[0][lk + 3][lr] = ra0.w;
    As[0][lk + 0][lr + 64] = ra1.x; As[0][lk + 1][lr + 64] = ra1.y;
    As[0][lk + 2][lr + 64] = ra1.z; As[0][lk + 3][lr + 64] = ra1.w;
    Bs[0][lk + 0][lr] = rb0.x; Bs[0][lk + 1][lr] = rb0.y;
    Bs[0][lk + 2][lr] = rb0.z; Bs[0][lk + 3][lr] = rb0.w;
    Bs[0][lk + 0][lr + 64] = rb1.x; Bs[0][lk + 1][lr + 64] = rb1.y;
    Bs[0][lk + 2][lr + 64] = rb1.z; Bs[0][lk + 3][lr + 64] = rb1.w;
    __syncthreads();

    const int nT = K / BK;
    for (int t = 0; t < nT; t++) {
        const int cur = t & 1;

        // prefetch next tile from gmem into registers (overlaps compute)
        if (t + 1 < nT) {
            const int ko = (t + 1) * BK;
            ra0 = *(const float4*)(gA0 + ko);
            ra1 = *(const float4*)(gA1 + ko);
            rb0 = *(const float4*)(gB0 + ko);
            rb1 = *(const float4*)(gB1 + ko);
        }

        #pragma unroll
        for (int k = 0; k < BK; k++) {
            float4 a0 = *(const float4*)&As[cur][k][m0];
            float4 a1 = *(const float4*)&As[cur][k][m0 + 4];
            const ulonglong2* bp = (const ulonglong2*)&Bs[cur][k][n0];
            ulonglong2 bq0 = bp[0];
            ulonglong2 bq1 = bp[1];
            u64 b0 = bq0.x, b1 = bq0.y, b2 = bq1.x, b3 = bq1.y;

            float am[8] = {a0.x, a0.y, a0.z, a0.w, a1.x, a1.y, a1.z, a1.w};
            #pragma unroll
            for (int i = 0; i < 8; i++) {
                u64 ap = pack2(am[i]);
                acc[i][0] = ffma2(ap, b0, acc[i][0]);
                acc[i][1] = ffma2(ap, b1, acc[i][1]);
                acc[i][2] = ffma2(ap, b2, acc[i][2]);
                acc[i][3] = ffma2(ap, b3, acc[i][3]);
            }
        }

        if (t + 1 < nT) {
            const int nxt = cur ^ 1;
            As[nxt][lk + 0][lr] = ra0.x; As[nxt][lk + 1][lr] = ra0.y;
            As[nxt][lk + 2][lr] = ra0.z; As[nxt][lk + 3][lr] = ra0.w;
            As[nxt][lk + 0][lr + 64] = ra1.x; As[nxt][lk + 1][lr + 64] = ra1.y;
            As[nxt][lk + 2][lr + 64] = ra1.z; As[nxt][lk + 3][lr + 64] = ra1.w;
            Bs[nxt][lk + 0][lr] = rb0.x; Bs[nxt][lk + 1][lr] = rb0.y;
            Bs[nxt][lk + 2][lr] = rb0.z; Bs[nxt][lk + 3][lr] = rb0.w;
            Bs[nxt][lk + 0][lr + 64] = rb1.x; Bs[nxt][lk + 1][lr + 64] = rb1.y;
            Bs[nxt][lk + 2][lr + 64] = rb1.z; Bs[nxt][lk + 3][lr + 64] = rb1.w;
            __syncthreads();
        }
    }

    // ---- epilogue: add bias, store 8x8 tile with float4 stores
    float bj[8];
    {
        float4 v0 = *(const float4*)(bias + bn + n0);
        float4 v1 = *(const float4*)(bias + bn + n0 + 4);
        bj[0] = v0.x; bj[1] = v0.y; bj[2] = v0.z; bj[3] = v0.w;
        bj[4] = v1.x; bj[5] = v1.y; bj[6] = v1.z; bj[7] = v1.w;
    }

    #pragma unroll
    for (int i = 0; i < 8; i++) {
        float r[8];
        #pragma unroll
        for (int j = 0; j < 4; j++)
            unpack2(acc[i][j], r[2 * j], r[2 * j + 1]);

        float4 o0, o1;
        o0.x = r[0] + bj[0]; o0.y = r[1] + bj[1];
        o0.z = r[2] + bj[2]; o0.w = r[3] + bj[3];
        o1.x = r[4] + bj[4]; o1.y = r[5] + bj[5];
        o1.z = r[6] + bj[6]; o1.w = r[7] + bj[7];

        float* crow = C + (size_t)(bm + m0 + i) * N + bn + n0;
        *(float4*)(crow)     = o0;
        *(float4*)(crow + 4) = o1;
    }
}

// ---------------------------------------------------------------------------
extern "C" void kernel_launch(void* const* d_in, const int* in_sizes, int n_in,
                              void* d_out, int out_size) {
    const float* x    = (const float*)d_in[0];   // (4, 4096, 2048) fp32
    const float* W    = (const float*)d_in[1];   // (2048, 2048) fp32
    const float* bias = (const float*)d_in[2];   // (2048,) fp32
    float* out        = (float*)d_out;           // (4, 4096, 2048) fp32

    const int K = in_sizes[2];          // 2048 (= D_DIM)
    const int N = K;                    // output features = 2048
    const int M = in_sizes[0] / K;      // 16384 rows

    // 1) Hadamard-transform W rows into g_Wh (scale folded in)
    fwht_rows_kernel<<<K, 256>>>(W);

    // 2) GEMM: out = x @ g_Wh^T + bias
    dim3 grid(N / BN, M / BM);
    had_gemm_kernel<<<grid, 256>>>(x, bias, out, M, N, K);
}

// round 3
// speedup vs baseline: 3.0822x; 3.0822x over previous
#include <cuda_runtime.h>
#include <cuda_bf16.h>
#include <cstdint>

// out[m,o] = sum_d FWHT(x)[m,d] * W[o,d] / sqrt(D) + b[o]
// Hadamard symmetric => FWHT(x) @ W^T == x @ (FWHT_rows(W))^T.
// Pipeline: (1) FWHT W rows + bf16 hi/lo split, (2) split x to bf16 hi/lo,
// (3) HMMA (mma.sync m16n8k16 bf16) GEMM computing the 3-term split
//     Ahi*Bhi + Ahi*Blo + Alo*Bhi with fp32 accumulators.
// NOTE: harness compiles via plain compute_103 PTX target -> tcgen05/TMA
// are unavailable; mma.sync/ldmatrix/cp.async are the legal tensor path.

#define D_DIM 2048
#define M_ROWS 16384
#define KDIM 2048
#define NDIM 2048

#define BM 128
#define BN 128
#define BK 64
#define NCH (KDIM / BK)         // 32 k-chunks
#define STAGES 3
#define TILE_B 16384            // 128 rows x 128 bytes
#define STAGE_B (4 * TILE_B)    // A_hi, A_lo, B_hi, B_lo
#define SMEM_TOTAL (STAGES * STAGE_B)

// ---- device-global scratch (allocation APIs banned; statics are legal) ----
__device__ __nv_bfloat16 g_W_hi[(size_t)NDIM * KDIM];
__device__ __nv_bfloat16 g_W_lo[(size_t)NDIM * KDIM];
__device__ __nv_bfloat16 g_x_hi[(size_t)M_ROWS * KDIM];
__device__ __nv_bfloat16 g_x_lo[(size_t)M_ROWS * KDIM];

// ====================== PTX helpers (all plain-target legal) ======================
__device__ __forceinline__ uint32_t smem_u32(const void* p) {
    uint32_t a;
    asm("{ .reg .u64 t; cvta.to.shared.u64 t, %1; cvt.u32.u64 %0, t; }" : "=r"(a) : "l"(p));
    return a;
}
#define CP16(dst, src) \
    asm volatile("cp.async.cg.shared.global [%0], [%1], 16;" :: "r"(dst), "l"(src))
#define CP_COMMIT() asm volatile("cp.async.commit_group;" ::: "memory")
#define CP_WAIT1()  asm volatile("cp.async.wait_group 1;" ::: "memory")

#define LDSM4(r0, r1, r2, r3, addr) \
    asm volatile("ldmatrix.sync.aligned.m8n8.x4.shared.b16 {%0,%1,%2,%3}, [%4];" \
                 : "=r"(r0), "=r"(r1), "=r"(r2), "=r"(r3) : "r"(addr))

__device__ __forceinline__ void mma16816(float* c, const uint32_t* a,
                                         uint32_t b0, uint32_t b1) {
    asm volatile(
        "mma.sync.aligned.m16n8k16.row.col.f32.bf16.bf16.f32 "
        "{%0,%1,%2,%3}, {%4,%5,%6,%7}, {%8,%9}, {%0,%1,%2,%3};"
        : "+f"(c[0]), "+f"(c[1]), "+f"(c[2]), "+f"(c[3])
        : "r"(a[0]), "r"(a[1]), "r"(a[2]), "r"(a[3]), "r"(b0), "r"(b1));
}

// ====================== Kernel 1: FWHT rows of W + bf16 hi/lo split ======================
__global__ __launch_bounds__(256) void fwht_split_w(const float* __restrict__ W) {
    __shared__ float s[D_DIM];
    const float* row = W + (size_t)blockIdx.x * D_DIM;
    int tid = threadIdx.x;
    for (int i = tid; i < D_DIM; i += 256) s[i] = row[i];
    __syncthreads();
    #pragma unroll
    for (int lg = 0; lg < 11; lg++) {
        int h = 1 << lg;
        #pragma unroll
        for (int q = 0; q < (D_DIM / 2) / 256; q++) {
            int p = tid + q * 256;
            int i = ((p >> lg) << (lg + 1)) | (p & (h - 1));
            float a = s[i], c = s[i + h];
            s[i] = a + c;
            s[i + h] = a - c;
        }
        __syncthreads();
    }
    const float scale = 0.02209708691207961f;  // 1/sqrt(2048)
    size_t base = (size_t)blockIdx.x * D_DIM;
    for (int i = tid; i < D_DIM; i += 256) {
        float v = s[i] * scale;
        __nv_bfloat16 h = __float2bfloat16(v);
        g_W_hi[base + i] = h;
        g_W_lo[base + i] = __float2bfloat16(v - __bfloat162float(h));
    }
}

// ====================== Kernel 2: split x into bf16 hi/lo ======================
__global__ __launch_bounds__(256) void split_x(const float* __restrict__ x) {
    size_t i = (size_t)blockIdx.x * 256 + threadIdx.x;   // float4 index
    float4 v = ((const float4*)x)[i];
    __nv_bfloat162 h01 = __floats2bfloat162_rn(v.x, v.y);
    __nv_bfloat162 h23 = __floats2bfloat162_rn(v.z, v.w);
    float lx = v.x - __bfloat162float(h01.x);
    float ly = v.y - __bfloat162float(h01.y);
    float lz = v.z - __bfloat162float(h23.x);
    float lw = v.w - __bfloat162float(h23.y);
    ((__nv_bfloat162*)g_x_hi)[2 * i]     = h01;
    ((__nv_bfloat162*)g_x_hi)[2 * i + 1] = h23;
    ((__nv_bfloat162*)g_x_lo)[2 * i]     = __floats2bfloat162_rn(lx, ly);
    ((__nv_bfloat162*)g_x_lo)[2 * i + 1] = __floats2bfloat162_rn(lz, lw);
}

// ====================== Kernel 3: HMMA GEMM (3-term bf16 split) ======================
// 8 warps: warp_m = wid&3 (4), warp_n = wid>>2 (2). Warp tile 32(m) x 64(n).
// Per chunk per warp: 4 k-steps x (2 m16-tiles x 8 n8-tiles x 3 terms) HMMA.

__global__ __launch_bounds__(256, 1)
void had_gemm_hmma(const float* __restrict__ bias, float* __restrict__ C) {
    extern __shared__ __align__(1024) char smem[];
    const uint32_t sm0 = smem_u32(smem);

    const int tid  = threadIdx.x;
    const int lane = tid & 31;
    const int wid  = tid >> 5;
    const int wm   = wid & 3;
    const int wn   = wid >> 2;

    const int bm = blockIdx.y * BM;
    const int bn = blockIdx.x * BN;

    // ---- cp.async loader mapping: row = tid>>3 (+32*i), 16B chunk = tid&7 ----
    const int lr = tid >> 3;
    const int lc = tid & 7;
    const uint32_t swchunk = (uint32_t)((lc ^ (lr & 7)) << 4);

    const __nv_bfloat16* src[4];
    src[0] = g_x_hi + (size_t)(bm + lr) * KDIM + lc * 8;
    src[1] = g_x_lo + (size_t)(bm + lr) * KDIM + lc * 8;
    src[2] = g_W_hi + (size_t)(bn + lr) * KDIM + lc * 8;
    src[3] = g_W_lo + (size_t)(bn + lr) * KDIM + lc * 8;

    // ---- fp32 accumulators: [m16 tile][n8 tile][4] ----
    float acc[2][8][4];
    #pragma unroll
    for (int i = 0; i < 2; i++)
        #pragma unroll
        for (int j = 0; j < 8; j++)
            #pragma unroll
            for (int q = 0; q < 4; q++) acc[i][j][q] = 0.f;

    // ---- ldmatrix per-thread address components ----
    const int raBase = wm * 32 + (lane & 15);            // A row (tm adds 16)
    const int cA     = lane >> 4;                        // A chunk half (k8)
    const int rbBase = wn * 64 + (lane & 7) + ((lane >> 4) << 3);  // B row (g adds 16)
    const int cB     = (lane >> 3) & 1;

    // issue one stage of cp.async (4 tiles x 4 row-sweeps = 16 x 16B)
    auto issue = [&](int s, int t) {
        const uint32_t sb = sm0 + s * STAGE_B;
        const size_t ko = (size_t)t * BK;
        #pragma unroll
        for (int tt = 0; tt < 4; tt++) {
            #pragma unroll
            for (int i = 0; i < 4; i++) {
                uint32_t dst = sb + tt * TILE_B + (uint32_t)(lr + 32 * i) * 128 + swchunk;
                CP16(dst, src[tt] + ko + (size_t)(32 * i) * KDIM);
            }
        }
    };

    issue(0, 0); CP_COMMIT();
    issue(1, 1); CP_COMMIT();

    for (int t = 0; t < NCH; t++) {
        CP_WAIT1();
        __syncthreads();

        if (t + 2 < NCH) issue((t + 2) % STAGES, t + 2);
        CP_COMMIT();

        const uint32_t sb  = sm0 + (t % STAGES) * STAGE_B;
        const uint32_t aHi = sb;
        const uint32_t aLo = sb + TILE_B;
        const uint32_t bHi = sb + 2 * TILE_B;
        const uint32_t bLo = sb + 3 * TILE_B;

        #pragma unroll
        for (int ks = 0; ks < 4; ks++) {
            uint32_t ah[2][4], al[2][4], bh[4][4], bl[4][4];
            #pragma unroll
            for (int tm = 0; tm < 2; tm++) {
                const int r = raBase + tm * 16;
                const uint32_t off = (uint32_t)r * 128 +
                                     (uint32_t)(((2 * ks + cA) ^ (r & 7)) << 4);
                LDSM4(ah[tm][0], ah[tm][1], ah[tm][2], ah[tm][3], aHi + off);
                LDSM4(al[tm][0], al[tm][1], al[tm][2], al[tm][3], aLo + off);
            }
            #pragma unroll
            for (int g = 0; g < 4; g++) {
                const int r = rbBase + g * 16;
                const uint32_t off = (uint32_t)r * 128 +
                                     (uint32_t)(((2 * ks + cB) ^ (r & 7)) << 4);
                LDSM4(bh[g][0], bh[g][1], bh[g][2], bh[g][3], bHi + off);
                LDSM4(bl[g][0], bl[g][1], bl[g][2], bl[g][3], bLo + off);
            }
            #pragma unroll
            for (int tm = 0; tm < 2; tm++) {
                #pragma unroll
                for (int g = 0; g < 4; g++) {
                    #pragma unroll
                    for (int h = 0; h < 2; h++) {
                        const int j = g * 2 + h;
                        mma16816(acc[tm][j], ah[tm], bh[g][2 * h], bh[g][2 * h + 1]);
                        mma16816(acc[tm][j], ah[tm], bl[g][2 * h], bl[g][2 * h + 1]);
                        mma16816(acc[tm][j], al[tm], bh[g][2 * h], bh[g][2 * h + 1]);
                    }
                }
            }
        }
        __syncthreads();
    }

    // ---- epilogue: add bias, store ----
    float2 bv[8];
    #pragma unroll
    for (int j = 0; j < 8; j++) {
        const int n = bn + wn * 64 + j * 8 + 2 * (lane & 3);
        bv[j] = *(const float2*)(bias + n);
    }
    #pragma unroll
    for (int tm = 0; tm < 2; tm++) {
        const int r0 = bm + wm * 32 + tm * 16 + (lane >> 2);
        #pragma unroll
        for (int j = 0; j < 8; j++) {
            const int n = bn + wn * 64 + j * 8 + 2 * (lane & 3);
            float2 o0, o1;
            o0.x = acc[tm][j][0] + bv[j].x;
            o0.y = acc[tm][j][1] + bv[j].y;
            o1.x = acc[tm][j][2] + bv[j].x;
            o1.y = acc[tm][j][3] + bv[j].y;
            *(float2*)(C + (size_t)r0 * NDIM + n)       = o0;
            *(float2*)(C + (size_t)(r0 + 8) * NDIM + n) = o1;
        }
    }
}

// ====================== host launch ======================
extern "C" void kernel_launch(void* const* d_in, const int* in_sizes, int n_in,
                              void* d_out, int out_size) {
    const float* x    = (const float*)d_in[0];   // (4,4096,2048) fp32
    const float* W    = (const float*)d_in[1];   // (2048,2048) fp32
    const float* bias = (const float*)d_in[2];   // (2048,) fp32
    float* out        = (float*)d_out;

    static bool attr_set = false;
    if (!attr_set) {
        cudaFuncSetAttribute(had_gemm_hmma, cudaFuncAttributeMaxDynamicSharedMemorySize,
                             SMEM_TOTAL);
        attr_set = true;
    }

    // 1) FWHT W rows + bf16 split
    fwht_split_w<<<D_DIM, 256>>>(W);
    // 2) split x into bf16 hi/lo
    split_x<<<(M_ROWS * D_DIM / 4) / 256, 256>>>(x);
    // 3) HMMA GEMM + bias (bn fastest for L2 reuse of x stripes)
    dim3 grid(NDIM / BN, M_ROWS / BM);
    had_gemm_hmma<<<grid, 256, SMEM_TOTAL>>>(bias, out);
}

// round 6
// speedup vs baseline: 7.5511x; 2.4499x over previous
#include <cuda_runtime.h>
#include <cuda_fp16.h>
#include <cstdint>

// out[m,o] = sum_d FWHT(x)[m,d] * W[o,d] / sqrt(D) + b[o]
// Hadamard symmetric => FWHT(x) @ W^T == x @ (FWHT_rows(W))^T.
// fp16 single-pass: x->fp16, FWHT(W)/sqrt(D)->fp16, one HMMA GEMM w/ fp32 acc.
// Pipeline: round-3 proven multistage pattern (prefetch distance 2, 3 stages;
// the round-5 failure was distance==STAGES aliasing the compute stage).

#define D_DIM 2048
#define M_ROWS 16384
#define KDIM 2048
#define NDIM 2048

#define BM 128
#define BN 128
#define BK 64
#define NCH (KDIM / BK)         // 32 k-chunks
#define STAGES 3
#define TILE_B 16384            // 128 rows x 128 bytes (64 halves)
#define STAGE_B (2 * TILE_B)    // A, B
#define SMEM_TOTAL (STAGES * STAGE_B)   // 96 KB -> 2 CTAs/SM

// ---- device-global scratch ----
__device__ __half g_W_h[(size_t)NDIM * KDIM];     // 8 MB
__device__ __half g_x_h[(size_t)M_ROWS * KDIM];   // 64 MB

// ====================== PTX helpers ======================
__device__ __forceinline__ uint32_t smem_u32(const void* p) {
    uint32_t a;
    asm("{ .reg .u64 t; cvta.to.shared.u64 t, %1; cvt.u32.u64 %0, t; }" : "=r"(a) : "l"(p));
    return a;
}
#define CP16(dst, src) \
    asm volatile("cp.async.cg.shared.global [%0], [%1], 16;" :: "r"(dst), "l"(src))
#define CP_COMMIT() asm volatile("cp.async.commit_group;" ::: "memory")
#define CP_WAIT1()  asm volatile("cp.async.wait_group 1;" ::: "memory")

#define LDSM4(r0, r1, r2, r3, addr) \
    asm volatile("ldmatrix.sync.aligned.m8n8.x4.shared.b16 {%0,%1,%2,%3}, [%4];" \
                 : "=r"(r0), "=r"(r1), "=r"(r2), "=r"(r3) : "r"(addr))

__device__ __forceinline__ void mma16816(float* c, const uint32_t* a,
                                         uint32_t b0, uint32_t b1) {
    asm volatile(
        "mma.sync.aligned.m16n8k16.row.col.f32.f16.f16.f32 "
        "{%0,%1,%2,%3}, {%4,%5,%6,%7}, {%8,%9}, {%0,%1,%2,%3};"
        : "+f"(c[0]), "+f"(c[1]), "+f"(c[2]), "+f"(c[3])
        : "r"(a[0]), "r"(a[1]), "r"(a[2]), "r"(a[3]), "r"(b0), "r"(b1));
}

// ====================== Kernel 1: FWHT rows of W -> fp16 (scale folded) ======================
__global__ __launch_bounds__(256) void fwht_w_f16(const float* __restrict__ W) {
    __shared__ float s[D_DIM];
    const float* row = W + (size_t)blockIdx.x * D_DIM;
    int tid = threadIdx.x;
    for (int i = tid; i < D_DIM; i += 256) s[i] = row[i];
    __syncthreads();
    #pragma unroll
    for (int lg = 0; lg < 11; lg++) {
        int h = 1 << lg;
        #pragma unroll
        for (int q = 0; q < (D_DIM / 2) / 256; q++) {
            int p = tid + q * 256;
            int i = ((p >> lg) << (lg + 1)) | (p & (h - 1));
            float a = s[i], c = s[i + h];
            s[i] = a + c;
            s[i + h] = a - c;
        }
        __syncthreads();
    }
    const float scale = 0.02209708691207961f;  // 1/sqrt(2048)
    size_t base = (size_t)blockIdx.x * D_DIM;
    for (int i = tid; i < D_DIM; i += 256)
        g_W_h[base + i] = __float2half_rn(s[i] * scale);
}

// ====================== Kernel 2: x -> fp16 ======================
__global__ __launch_bounds__(256) void x_to_f16(const float* __restrict__ x) {
    size_t i = (size_t)blockIdx.x * 256 + threadIdx.x;   // float4 index
    float4 v = ((const float4*)x)[i];
    ((__half2*)g_x_h)[2 * i]     = __floats2half2_rn(v.x, v.y);
    ((__half2*)g_x_h)[2 * i + 1] = __floats2half2_rn(v.z, v.w);
}

// ====================== Kernel 3: fp16 HMMA GEMM + bias ======================
// 8 warps: warp_m = wid&3, warp_n = wid>>2. Warp tile 32(m) x 64(n).
// Per chunk per warp: 4 k16-steps x (2 m16 x 8 n8) HMMA = 64 MMA, 12 LDSM4.

__global__ __launch_bounds__(256, 2)
void had_gemm_f16(const float* __restrict__ bias, float* __restrict__ C) {
    extern __shared__ __align__(1024) char smem[];
    const uint32_t sm0 = smem_u32(smem);

    const int tid  = threadIdx.x;
    const int lane = tid & 31;
    const int wid  = tid >> 5;
    const int wm   = wid & 3;
    const int wn   = wid >> 2;

    const int bm = blockIdx.y * BM;
    const int bn = blockIdx.x * BN;

    // ---- cp.async loader mapping ----
    const int lr = tid >> 3;      // 0..31 (+32*i)
    const int lc = tid & 7;       // 16B chunk
    const uint32_t swchunk = (uint32_t)((lc ^ (lr & 7)) << 4);

    const __half* srcA = g_x_h + (size_t)(bm + lr) * KDIM + lc * 8;
    const __half* srcB = g_W_h + (size_t)(bn + lr) * KDIM + lc * 8;

    float acc[2][8][4];
    #pragma unroll
    for (int i = 0; i < 2; i++)
        #pragma unroll
        for (int j = 0; j < 8; j++)
            #pragma unroll
            for (int q = 0; q < 4; q++) acc[i][j][q] = 0.f;

    // ---- ldmatrix per-thread address components ----
    const int raBase = wm * 32 + (lane & 15);
    const int cA     = lane >> 4;
    const int rbBase = wn * 64 + (lane & 7) + ((lane >> 4) << 3);
    const int cB     = (lane >> 3) & 1;

    auto issue = [&](int s, int t) {
        const uint32_t sb = sm0 + s * STAGE_B;
        const size_t ko = (size_t)t * BK;
        #pragma unroll
        for (int i = 0; i < 4; i++) {
            uint32_t roff = (uint32_t)(lr + 32 * i) * 128 + swchunk;
            CP16(sb + roff, srcA + ko + (size_t)(32 * i) * KDIM);
            CP16(sb + TILE_B + roff, srcB + ko + (size_t)(32 * i) * KDIM);
        }
    };

    // prologue: distance-2 prefetch (stage for compute-t is NEVER written
    // in iteration t: writes go to (t+2)%3 != t%3)
    issue(0, 0); CP_COMMIT();
    issue(1, 1); CP_COMMIT();

    for (int t = 0; t < NCH; t++) {
        CP_WAIT1();
        __syncthreads();

        if (t + 2 < NCH) issue((t + 2) % STAGES, t + 2);
        CP_COMMIT();

        const uint32_t sb = sm0 + (t % STAGES) * STAGE_B;
        const uint32_t aT = sb;
        const uint32_t bT = sb + TILE_B;

        #pragma unroll
        for (int ks = 0; ks < 4; ks++) {
            uint32_t ah[2][4], bh[4][4];
            #pragma unroll
            for (int tm = 0; tm < 2; tm++) {
                const int r = raBase + tm * 16;
                const uint32_t off = (uint32_t)r * 128 +
                                     (uint32_t)(((2 * ks + cA) ^ (r & 7)) << 4);
                LDSM4(ah[tm][0], ah[tm][1], ah[tm][2], ah[tm][3], aT + off);
            }
            #pragma unroll
            for (int g = 0; g < 4; g++) {
                const int r = rbBase + g * 16;
                const uint32_t off = (uint32_t)r * 128 +
                                     (uint32_t)(((2 * ks + cB) ^ (r & 7)) << 4);
                LDSM4(bh[g][0], bh[g][1], bh[g][2], bh[g][3], bT + off);
            }
            #pragma unroll
            for (int tm = 0; tm < 2; tm++) {
                #pragma unroll
                for (int g = 0; g < 4; g++) {
                    #pragma unroll
                    for (int h = 0; h < 2; h++) {
                        mma16816(acc[tm][g * 2 + h], ah[tm], bh[g][2 * h], bh[g][2 * h + 1]);
                    }
                }
            }
        }
        __syncthreads();
    }

    // ---- epilogue: add bias, store ----
    float2 bv[8];
    #pragma unroll
    for (int j = 0; j < 8; j++) {
        const int n = bn + wn * 64 + j * 8 + 2 * (lane & 3);
        bv[j] = *(const float2*)(bias + n);
    }
    #pragma unroll
    for (int tm = 0; tm < 2; tm++) {
        const int r0 = bm + wm * 32 + tm * 16 + (lane >> 2);
        #pragma unroll
        for (int j = 0; j < 8; j++) {
            const int n = bn + wn * 64 + j * 8 + 2 * (lane & 3);
            float2 o0, o1;
            o0.x = acc[tm][j][0] + bv[j].x;
            o0.y = acc[tm][j][1] + bv[j].y;
            o1.x = acc[tm][j][2] + bv[j].x;
            o1.y = acc[tm][j][3] + bv[j].y;
            *(float2*)(C + (size_t)r0 * NDIM + n)       = o0;
            *(float2*)(C + (size_t)(r0 + 8) * NDIM + n) = o1;
        }
    }
}

// ====================== host launch ======================
extern "C" void kernel_launch(void* const* d_in, const int* in_sizes, int n_in,
                              void* d_out, int out_size) {
    const float* x    = (const float*)d_in[0];   // (4,4096,2048) fp32
    const float* W    = (const float*)d_in[1];   // (2048,2048) fp32
    const float* bias = (const float*)d_in[2];   // (2048,) fp32
    float* out        = (float*)d_out;

    static bool attr_set = false;
    if (!attr_set) {
        cudaFuncSetAttribute(had_gemm_f16, cudaFuncAttributeMaxDynamicSharedMemorySize,
                             SMEM_TOTAL);
        attr_set = true;
    }

    fwht_w_f16<<<D_DIM, 256>>>(W);
    x_to_f16<<<(M_ROWS * KDIM / 4) / 256, 256>>>(x);
    dim3 grid(NDIM / BN, M_ROWS / BM);   // bn fastest -> x-stripe L2 reuse
    had_gemm_f16<<<grid, 256, SMEM_TOTAL>>>(bias, out);
}